// round 14
// baseline (speedup 1.0000x reference)
#include <cuda_runtime.h>
#include <cuda_fp16.h>
#include <math.h>

#define BB   32
#define LQ   512
#define DD   384
#define FF   384
#define MROWS (BB*LQ)      // 16384
#define KDIM  (DD*3)       // 1152 halves
#define LN_EPS 1e-5f
#define STAGES 3
#define RSH 40             // smem row stride in halves (80 B, odd 16B-chunk count)
#define GEMM_BLOCKS ((MROWS/64)*(FF/64))    // 1536
#define NPX2 (MROWS*DD/2/256)               // 12288
#define NWR (FF*2)                          // 768

// Scratch (no allocations allowed).
__device__ float  g_buf1[(size_t)MROWS * FF];
__device__ __half g_buf2h[(size_t)MROWS * FF];
__device__ __half g_xph [(size_t)MROWS * DD];
__device__ __half g_w1rh[(size_t)FF * KDIM];
__device__ __half g_w2rh[(size_t)FF * KDIM];
__device__ int    g_fidx[BB * 8192];        // frame -> source phoneme (-1 = pad)

// ---------------------------------------------------------------------------
// Fused prep: natural k-order everywhere (ldmatrix handles fragment shuffle).
// ---------------------------------------------------------------------------
__global__ __launch_bounds__(256) void prep_all_kernel(
    const float* __restrict__ x, __half* __restrict__ xp,
    const float* __restrict__ W1, __half* __restrict__ Wr1,
    const float* __restrict__ W2, __half* __restrict__ Wr2,
    const int* __restrict__ target, int M)
{
    const int bidx = blockIdx.x;
    const int t = threadIdx.x;

    if (bidx < NPX2) {
        const int i2 = bidx * 256 + t;
        const float2 v = *(const float2*)&x[(size_t)i2 * 2];
        *(__half2*)&xp[(size_t)i2 * 2] = __floats2half2_rn(v.x, v.y);
    } else if (bidx < NPX2 + NWR) {
        const int r2 = bidx - NPX2;
        const float* W  = (r2 >= FF) ? W2 : W1;
        __half*     Wr = (r2 >= FF) ? Wr2 : Wr1;
        const int f = (r2 >= FF) ? r2 - FF : r2;
        for (int i = t; i < KDIM; i += 256) {
            const int kseg = i / DD;
            const int d    = i - kseg * DD;
            Wr[(size_t)f * KDIM + i] =
                __float2half_rn(W[(size_t)f * KDIM + d * 3 + kseg]);
        }
    } else {
        __shared__ int s[512];
        const int fb  = bidx - (NPX2 + NWR);
        const int bpB = M >> 8;
        const int b   = fb / bpB;
        const int fr0 = (fb - b * bpB) * 256;
        s[t]       = target[b * LQ + t];
        s[t + 256] = target[b * LQ + t + 256];
        __syncthreads();
        for (int off = 1; off < 512; off <<= 1) {
            const int v0 = (t >= off) ? s[t - off] : 0;
            const int v1 = s[t + 256 - off];
            __syncthreads();
            s[t] += v0;
            s[t + 256] += v1;
            __syncthreads();
        }
        const int fr = fr0 + t;
        const int total = s[511];
        int idx = -1;
        if (fr < total) {
            int lo = 0, hi = LQ;
            while (lo < hi) {
                const int mid = (lo + hi) >> 1;
                if (s[mid] <= fr) lo = mid + 1; else hi = mid;
            }
            idx = min(lo, LQ - 1);
        }
        g_fidx[b * M + fr] = idx;
    }
}

__device__ __forceinline__ void mma_f16(float c[4], unsigned a0, unsigned a1,
                                        unsigned a2, unsigned a3,
                                        unsigned b0, unsigned b1)
{
    asm volatile(
        "mma.sync.aligned.m16n8k16.row.col.f32.f16.f16.f32 "
        "{%0,%1,%2,%3}, {%4,%5,%6,%7}, {%8,%9}, {%0,%1,%2,%3};"
        : "+f"(c[0]), "+f"(c[1]), "+f"(c[2]), "+f"(c[3])
        : "r"(a0), "r"(a1), "r"(a2), "r"(a3), "r"(b0), "r"(b1));
}

__device__ __forceinline__ void ldsm4(unsigned r[4], unsigned addr)
{
    asm volatile("ldmatrix.sync.aligned.m8n8.x4.shared.b16 {%0,%1,%2,%3}, [%4];"
                 : "=r"(r[0]), "=r"(r[1]), "=r"(r[2]), "=r"(r[3]) : "r"(addr));
}

__device__ __forceinline__ void cp16(unsigned dst, const void* src, bool p)
{
    const int sz = p ? 16 : 0;
    asm volatile("cp.async.cg.shared.global [%0], [%1], 16, %2;\n"
                 :: "r"(dst), "l"(src), "r"(sz));
}

// ---------------------------------------------------------------------------
// Conv fp16 mma via ldmatrix: CTA 64x64, BK=32, 128 threads, 4 warps 2x2
// (warp 32x32). Per warp-iter: 8 LDSM.x4 + 16 MMA (was 24 LDS.64 + 16 MMA).
// 3-stage cp.async, 6 CTAs/SM. Blocks >= GEMM_BLOCKS: expand via g_fidx.
// ---------------------------------------------------------------------------
__global__ __launch_bounds__(128, 6) void conv_expand_kernel(
    const __half* __restrict__ Asrc, const __half* __restrict__ Wr,
    const float* __restrict__ bias, float* __restrict__ Y,
    const float* __restrict__ X, float* __restrict__ out,
    int M, int exp_base)
{
    if (blockIdx.x >= GEMM_BLOCKS) {
        const int g   = blockIdx.x - GEMM_BLOCKS + exp_base;
        const int gpb = M >> 3;
        const int b   = g / gpb;
        const int fg  = g - b * gpb;
        const int* fi = g_fidx + b * M + fg * 8;
        float4* obase = (float4*)(out + (size_t)b * M * DD) + (size_t)fg * 768;
        #pragma unroll
        for (int i = 0; i < 6; ++i) {
            const int idx  = i * 128 + threadIdx.x;
            const int fr8  = idx / 96;
            const int lane = idx - fr8 * 96;
            const int sidx = __ldg(&fi[fr8]);
            if (sidx < 0) {
                __stcs(&obase[idx], make_float4(0.f, 0.f, 0.f, 0.f));
            } else {
                const float4* src = (const float4*)(X + ((size_t)b * LQ + sidx) * DD);
                __stcs(&obase[idx], __ldg(&src[lane]));
            }
        }
        return;
    }

    // ---------------- conv ----------------
    extern __shared__ __half smh[];
    __half* As = smh;                          // [STAGES][64][RSH]
    __half* Bs = smh + STAGES * 64 * RSH;      // [STAGES][64][RSH]

    const int m0 = (blockIdx.x & 255) * 64;
    const int f0 = (blockIdx.x >> 8) * 64;
    const int t  = threadIdx.x;
    const int lane = t & 31, grp = lane >> 2, tig = lane & 3;
    const int warp = t >> 5;
    const int m_base = (warp & 1) * 32;
    const int n_base = (warp >> 1) * 32;

    // loader mapping
    const int lrow = t >> 2;            // 0..31
    const int c    = t & 3;             // 16B chunk (8 halves)

    int bA[2], lA[2];
    #pragma unroll
    for (int rr = 0; rr < 2; ++rr) {
        const int m = m0 + lrow + rr * 32;
        bA[rr] = m >> 9;
        lA[rr] = m & 511;
    }

    const unsigned ROWB  = RSH * 2;          // 80
    const unsigned STB   = 64 * ROWB;        // 5120 per stage (A or B)
    const unsigned aAd0 = (unsigned)__cvta_generic_to_shared(&As[0]) + lrow * ROWB + c * 16;
    const unsigned bAd0 = (unsigned)__cvta_generic_to_shared(&Bs[0]) + lrow * ROWB + c * 16;
    const unsigned ROW32 = 32 * ROWB;

    const __half* wr0 = Wr + (size_t)(f0 + lrow) * KDIM + c * 8;
    const __half* wr1 = Wr + (size_t)(f0 + lrow + 32) * KDIM + c * 8;

    // ldmatrix per-thread base addresses
    const int lg = lane >> 3, lr = lane & 7;
    const unsigned aLd = (unsigned)__cvta_generic_to_shared(&As[0])
        + (m_base + (lg & 1) * 8 + lr) * ROWB + (lg >> 1) * 16;
    const unsigned bLd = (unsigned)__cvta_generic_to_shared(&Bs[0])
        + (n_base + (lg >> 1) * 8 + lr) * ROWB + (lg & 1) * 16;

    float acc[2][4][4] = {};

    auto load_tile = [&](int it, int st) {
        const int kk0  = it * 32;
        const int kseg = (kk0 >= 384) + (kk0 >= 768);
        const int off  = kk0 - kseg * DD + c * 8;
        #pragma unroll
        for (int rr = 0; rr < 2; ++rr) {
            const int l2 = lA[rr] + kseg - 1;
            const bool v = (l2 >= 0) & (l2 < LQ);
            const __half* sa = Asrc + ((size_t)(bA[rr] << 9) + (v ? l2 : 0)) * DD + off;
            cp16(aAd0 + st * STB + rr * ROW32, sa, v);
        }
        cp16(bAd0 + st * STB,         wr0 + kk0, true);
        cp16(bAd0 + st * STB + ROW32, wr1 + kk0, true);
    };

    load_tile(0, 0);
    asm volatile("cp.async.commit_group;");
    load_tile(1, 1);
    asm volatile("cp.async.commit_group;");
    asm volatile("cp.async.wait_group 1;");
    __syncthreads();

    const int NIT = KDIM / 32;   // 36
    int st_next = 2, buf = 0;
    for (int it = 0; it < NIT; ++it) {
        if (it + 2 < NIT) load_tile(it + 2, st_next);
        asm volatile("cp.async.commit_group;");
        if (++st_next == STAGES) st_next = 0;

        const unsigned aB = aLd + buf * STB;
        const unsigned bB = bLd + buf * STB;
        #pragma unroll
        for (int ks = 0; ks < 2; ++ks) {
            unsigned b0[4], b1[4];
            ldsm4(b0, bB + ks * 32);                  // nt0,nt1 (rows n_base..+15)
            ldsm4(b1, bB + 16 * ROWB + ks * 32);      // nt2,nt3
            #pragma unroll
            for (int mt = 0; mt < 2; ++mt) {
                unsigned a[4];
                ldsm4(a, aB + mt * 16 * ROWB + ks * 32);
                mma_f16(acc[mt][0], a[0], a[1], a[2], a[3], b0[0], b0[1]);
                mma_f16(acc[mt][1], a[0], a[1], a[2], a[3], b0[2], b0[3]);
                mma_f16(acc[mt][2], a[0], a[1], a[2], a[3], b1[0], b1[1]);
                mma_f16(acc[mt][3], a[0], a[1], a[2], a[3], b1[2], b1[3]);
            }
        }
        if (++buf == STAGES) buf = 0;

        asm volatile("cp.async.wait_group 1;");
        __syncthreads();
    }

    #pragma unroll
    for (int mt = 0; mt < 2; ++mt) {
        const int mrow = m0 + m_base + mt * 16 + grp;
        #pragma unroll
        for (int nt = 0; nt < 4; ++nt) {
            const int fc = f0 + n_base + nt * 8 + 2 * tig;
            const float b0v = bias[fc], b1v = bias[fc + 1];
            float2 r0 = make_float2(acc[mt][nt][0] + b0v, acc[mt][nt][1] + b1v);
            float2 r1 = make_float2(acc[mt][nt][2] + b0v, acc[mt][nt][3] + b1v);
            *(float2*)&Y[(size_t)mrow * FF + fc] = r0;
            *(float2*)&Y[(size_t)(mrow + 8) * FF + fc] = r1;
        }
    }
}

// ---------------------------------------------------------------------------
__device__ __forceinline__ float2 row_reduce2(float s, float q, float* sh8)
{
    __syncthreads();
    const int lane = threadIdx.x & 31;
    const int w    = threadIdx.x >> 5;
    #pragma unroll
    for (int o = 16; o > 0; o >>= 1) {
        s += __shfl_down_sync(0xffffffffu, s, o);
        q += __shfl_down_sync(0xffffffffu, q, o);
    }
    if (lane == 0) { sh8[w] = s; sh8[4 + w] = q; }
    __syncthreads();
    if (threadIdx.x == 0) {
        sh8[0] = sh8[0] + sh8[1] + sh8[2] + sh8[3];
        sh8[4] = sh8[4] + sh8[5] + sh8[6] + sh8[7];
    }
    __syncthreads();
    return make_float2(sh8[0], sh8[4]);
}

// LN+ReLU -> fp16 natural order; 4 rows per block, 128 thr per row.
__global__ __launch_bounds__(512) void ln_relu_kernel(
    const float* __restrict__ In, const float* __restrict__ gam,
    const float* __restrict__ bet, __half* __restrict__ Out)
{
    __shared__ float sh[4][8];
    const int row = blockIdx.x * 4 + threadIdx.y;
    const int t   = threadIdx.x;
    const float* p = In + (size_t)row * FF;
    float v0 = p[t], v1 = p[t + 128], v2 = p[t + 256];
    float2 r = row_reduce2(v0 + v1 + v2, v0 * v0 + v1 * v1 + v2 * v2,
                           sh[threadIdx.y]);
    const float mu  = r.x * (1.0f / FF);
    const float var = r.y * (1.0f / FF) - mu * mu;
    const float rs  = rsqrtf(var + LN_EPS);
    __half* o = Out + (size_t)row * FF;
    float v[3] = {v0, v1, v2};
    #pragma unroll
    for (int i = 0; i < 3; i++) {
        const int f = t + i * 128;
        const float h = fmaxf((v[i] - mu) * rs * gam[f] + bet[f], 0.0f);
        o[f] = __float2half_rn(h);
    }
}

__global__ __launch_bounds__(512) void ln_linear_kernel(
    const float* __restrict__ In, const float* __restrict__ gam,
    const float* __restrict__ bet, const float* __restrict__ lw,
    const float* __restrict__ lb, float* __restrict__ dur)
{
    __shared__ float sh[4][8];
    const int row = blockIdx.x * 4 + threadIdx.y;
    const int t   = threadIdx.x;
    const float* p = In + (size_t)row * FF;
    float v0 = p[t], v1 = p[t + 128], v2 = p[t + 256];
    float2 r = row_reduce2(v0 + v1 + v2, v0 * v0 + v1 * v1 + v2 * v2,
                           sh[threadIdx.y]);
    const float mu  = r.x * (1.0f / FF);
    const float var = r.y * (1.0f / FF) - mu * mu;
    const float rs  = rsqrtf(var + LN_EPS);
    float v[3] = {v0, v1, v2};
    float acc = 0.0f;
    #pragma unroll
    for (int i = 0; i < 3; i++) {
        const int f = t + i * 128;
        float h = fmaxf((v[i] - mu) * rs * gam[f] + bet[f], 0.0f);
        acc += h * lw[f];
    }
    float2 r2 = row_reduce2(acc, 0.0f, sh[threadIdx.y]);
    if (t == 0) dur[row] = fmaxf(r2.x + lb[0], 0.0f);
}

// ---------------------------------------------------------------------------
extern "C" void kernel_launch(void* const* d_in, const int* in_sizes, int n_in,
                              void* d_out, int out_size)
{
    const float* x     = (const float*)d_in[0];
    const float* c1_w  = (const float*)d_in[1];
    const float* c1_b  = (const float*)d_in[2];
    const float* ln1_g = (const float*)d_in[3];
    const float* ln1_b = (const float*)d_in[4];
    const float* c2_w  = (const float*)d_in[5];
    const float* c2_b  = (const float*)d_in[6];
    const float* ln2_g = (const float*)d_in[7];
    const float* ln2_b = (const float*)d_in[8];
    const float* lin_w = (const float*)d_in[9];
    const float* lin_b = (const float*)d_in[10];
    const int*   target= (const int*)d_in[11];

    const int M = (out_size - BB * LQ) / (BB * DD);

    float*  buf1;  cudaGetSymbolAddress((void**)&buf1,  g_buf1);
    __half* buf2h; cudaGetSymbolAddress((void**)&buf2h, g_buf2h);
    __half* xph;   cudaGetSymbolAddress((void**)&xph,   g_xph);
    __half* w1rh;  cudaGetSymbolAddress((void**)&w1rh,  g_w1rh);
    __half* w2rh;  cudaGetSymbolAddress((void**)&w2rh,  g_w2rh);

    float* out_expand = (float*)d_out;
    float* out_dur    = (float*)d_out + (size_t)BB * M * DD;

    const int smem_bytes = STAGES * (64 + 64) * RSH * 2;  // 30720
    cudaFuncSetAttribute(conv_expand_kernel,
                         cudaFuncAttributeMaxDynamicSharedMemorySize, smem_bytes);

    const int nfi       = BB * (M >> 8);
    const int exp_total = BB * (M >> 3);
    const int exp_half  = exp_total / 2;

    prep_all_kernel<<<NPX2 + NWR + nfi, 256>>>(x, xph, c1_w, w1rh, c2_w, w2rh,
                                               target, M);
    conv_expand_kernel<<<GEMM_BLOCKS + exp_half, 128, smem_bytes>>>(
        xph, w1rh, c1_b, buf1, x, out_expand, M, 0);
    ln_relu_kernel<<<MROWS / 4, dim3(128, 4)>>>(buf1, ln1_g, ln1_b, buf2h);
    conv_expand_kernel<<<GEMM_BLOCKS + (exp_total - exp_half), 128, smem_bytes>>>(
        buf2h, w2rh, c2_b, buf1, x, out_expand, M, exp_half);
    ln_linear_kernel<<<MROWS / 4, dim3(128, 4)>>>(buf1, ln2_g, ln2_b, lin_w, lin_b, out_dur);
}